// round 4
// baseline (speedup 1.0000x reference)
#include <cuda_runtime.h>
#include <cuda_bf16.h>
#include <cstdint>

#define B_    8
#define N_    2048
#define F_    512
#define MTOT  (B_ * N_)          // 16384
#define NEGV  (-10000.0f)
#define SLOPE 0.2f
#define FULLM 0xFFFFFFFFu

// ---------------- device scratch (sanctioned static-array path) -------------
__device__ __nv_bfloat16 g_tHi[(size_t)MTOT * F_];
__device__ __nv_bfloat16 g_tLo[(size_t)MTOT * F_];
__device__ __nv_bfloat16 g_WHi[(size_t)F_ * F_];
__device__ __nv_bfloat16 g_WLo[(size_t)F_ * F_];
__device__ __nv_bfloat16 g_hHi[(size_t)MTOT * F_];   // hidden split, row-major
__device__ __nv_bfloat16 g_hLo[(size_t)MTOT * F_];
__device__ float g_sv[MTOT], g_dv[MTOT];
__device__ __nv_bfloat16 g_PHi[(size_t)MTOT * N_];
__device__ __nv_bfloat16 g_PLo[(size_t)MTOT * N_];

// ---------------- base-target PTX helpers ------------------------------------
__device__ __forceinline__ uint32_t smem_u32(const void* p) {
    uint32_t a;
    asm("{ .reg .u64 t; cvta.to.shared.u64 t, %1; cvt.u32.u64 %0, t; }"
        : "=r"(a) : "l"(p));
    return a;
}
__device__ __forceinline__ void cp16(uint32_t dst, const void* src) {
    asm volatile("cp.async.cg.shared.global [%0], [%1], 16;" :: "r"(dst), "l"(src));
}
#define CP_COMMIT() asm volatile("cp.async.commit_group;" ::: "memory")
#define CP_WAIT(n)  asm volatile("cp.async.wait_group %0;" :: "n"(n) : "memory")

#define LDSM4(r0, r1, r2, r3, addr) \
    asm volatile("ldmatrix.sync.aligned.m8n8.x4.shared.b16 {%0,%1,%2,%3}, [%4];" \
                 : "=r"(r0), "=r"(r1), "=r"(r2), "=r"(r3) : "r"(addr))
#define LDSM4T(r0, r1, r2, r3, addr) \
    asm volatile("ldmatrix.sync.aligned.m8n8.x4.trans.shared.b16 {%0,%1,%2,%3}, [%4];" \
                 : "=r"(r0), "=r"(r1), "=r"(r2), "=r"(r3) : "r"(addr))

#define MMA(d, a, b) \
    asm volatile("mma.sync.aligned.m16n8k16.row.col.f32.bf16.bf16.f32 " \
                 "{%0,%1,%2,%3}, {%4,%5,%6,%7}, {%8,%9}, {%0,%1,%2,%3};" \
                 : "+f"((d)[0]), "+f"((d)[1]), "+f"((d)[2]), "+f"((d)[3]) \
                 : "r"((a)[0]), "r"((a)[1]), "r"((a)[2]), "r"((a)[3]), \
                   "r"((b)[0]), "r"((b)[1]))

// ---------------- SMEM layout -------------------------------------------------
// A tile: 128 rows x 32 bf16, pitch 80 B  -> conflict-free ldmatrix
// B tile:  32 rows x 128 bf16, pitch 272 B
#define A_PITCH_B 80
#define B_PITCH_B 272
#define SZ_A (128 * A_PITCH_B)            // 10240
#define SZ_B (32 * B_PITCH_B)             // 8704
#define BUF_STRIDE (2 * SZ_A + 2 * SZ_B)  // 37888
#define STAGES 3
#define SMEM_BYTES (STAGES * BUF_STRIDE)  // 113664

// ---------------- 3-term split-bf16 GEMM (mma.sync), CTA 128x128x32 ----------
// C[m,n] = sum_k (Ahi+Alo)[m,k] * (Bhi+Blo)[k,n]   (lo*lo term dropped)
// mode 0: h = C + bias -> split into (hHi, hLo), row-major
// mode 1: outF[row][512] = C  (fp32)
__global__ __launch_bounds__(256) void gemm_mma(
    const __nv_bfloat16* __restrict__ Ahi, const __nv_bfloat16* __restrict__ Alo,
    const __nv_bfloat16* __restrict__ Bhi, const __nv_bfloat16* __restrict__ Blo,
    int lda, int ldb, int K, int AZ, int BZ, int mode,
    const float* __restrict__ bias, float* __restrict__ outF,
    __nv_bfloat16* __restrict__ hHi, __nv_bfloat16* __restrict__ hLo)
{
    extern __shared__ char sm[];
    const uint32_t smBase = smem_u32(sm);

    const int t = threadIdx.x;
    const int warp = t >> 5, lane = t & 31;
    const int wm = warp & 1, wn = warp >> 1;          // 2 x 4 warp grid

    const int nBase  = blockIdx.x * 128;
    const int aRow0  = blockIdx.y * 128 + blockIdx.z * AZ;
    const int bRow0  = blockIdx.z * BZ;

    float acc[4][4][4];
#pragma unroll
    for (int i = 0; i < 4; i++)
#pragma unroll
        for (int j = 0; j < 4; j++)
#pragma unroll
            for (int q = 0; q < 4; q++) acc[i][j][q] = 0.0f;

    // ---- per-thread load geometry (hoisted; per-tile math = adds only) ----
    const int rA = t >> 2, chA = t & 3;               // A rows rA, rA+64
    const int rB = t >> 4, chB = t & 15;              // B rows rB, rB+16
    const __nv_bfloat16* pAh = Ahi + (size_t)(aRow0 + rA) * lda + chA * 8;
    const __nv_bfloat16* pAl = Alo + (size_t)(aRow0 + rA) * lda + chA * 8;
    const __nv_bfloat16* pBh = Bhi + (size_t)(bRow0 + rB) * ldb + nBase + chB * 8;
    const __nv_bfloat16* pBl = Blo + (size_t)(bRow0 + rB) * ldb + nBase + chB * 8;
    const uint32_t sA = smBase + rA * A_PITCH_B + chA * 16;
    const uint32_t sB = smBase + 2 * SZ_A + rB * B_PITCH_B + chB * 16;
    const size_t a64 = (size_t)64 * lda;
    const size_t b16 = (size_t)16 * ldb;

    auto load_tile = [&](int buf, int kt) {
        const size_t ka = (size_t)kt * 32;
        const size_t kb = (size_t)kt * 32 * ldb;
        const uint32_t ob = buf * BUF_STRIDE;
        cp16(sA + ob,                          pAh + ka);
        cp16(sA + ob + 64 * A_PITCH_B,         pAh + ka + a64);
        cp16(sA + ob + SZ_A,                   pAl + ka);
        cp16(sA + ob + SZ_A + 64 * A_PITCH_B,  pAl + ka + a64);
        cp16(sB + ob,                          pBh + kb);
        cp16(sB + ob + 16 * B_PITCH_B,         pBh + kb + b16);
        cp16(sB + ob + SZ_B,                   pBl + kb);
        cp16(sB + ob + SZ_B + 16 * B_PITCH_B,  pBl + kb + b16);
    };

    // per-lane ldmatrix address components
    const int aRowL  = lane & 15;
    const int aColB  = (lane >> 4) * 16;
    const int bRowL  = lane & 15;
    const int bColB  = (wn * 32 + (lane >> 4) * 8) * 2;

    const int ntiles = K / 32;
    load_tile(0, 0); CP_COMMIT();
    load_tile(1, 1); CP_COMMIT();

    int buf = 0;
    for (int kt = 0; kt < ntiles; kt++) {
        if (kt < ntiles - 1) { CP_WAIT(1); } else { CP_WAIT(0); }
        __syncthreads();

        if (kt + 2 < ntiles) {
            int nb = buf + 2; if (nb >= STAGES) nb -= STAGES;
            load_tile(nb, kt + 2);
            CP_COMMIT();
        }

        const uint32_t ob  = smBase + buf * BUF_STRIDE;
        const uint32_t obB = ob + 2 * SZ_A;

#pragma unroll
        for (int ks = 0; ks < 2; ks++) {
            uint32_t ahi[4][4], alo[4][4];
#pragma unroll
            for (int mt = 0; mt < 4; mt++) {
                uint32_t ra = ob + (wm * 64 + mt * 16 + aRowL) * A_PITCH_B
                            + ks * 32 + aColB;
                LDSM4(ahi[mt][0], ahi[mt][1], ahi[mt][2], ahi[mt][3], ra);
                LDSM4(alo[mt][0], alo[mt][1], alo[mt][2], alo[mt][3], ra + SZ_A);
            }
            uint32_t bhi[4][2], blo[4][2];
#pragma unroll
            for (int bt = 0; bt < 2; bt++) {
                uint32_t rb = obB + (ks * 16 + bRowL) * B_PITCH_B + bColB + bt * 32;
                LDSM4T(bhi[bt*2][0], bhi[bt*2][1], bhi[bt*2+1][0], bhi[bt*2+1][1], rb);
                LDSM4T(blo[bt*2][0], blo[bt*2][1], blo[bt*2+1][0], blo[bt*2+1][1],
                       rb + SZ_B);
            }
            // term-major: 16 independent accumulators between same-acc reuse
#pragma unroll
            for (int mt = 0; mt < 4; mt++)
#pragma unroll
                for (int nt = 0; nt < 4; nt++)
                    MMA(acc[mt][nt], ahi[mt], bhi[nt]);
#pragma unroll
            for (int mt = 0; mt < 4; mt++)
#pragma unroll
                for (int nt = 0; nt < 4; nt++)
                    MMA(acc[mt][nt], alo[mt], bhi[nt]);
#pragma unroll
            for (int mt = 0; mt < 4; mt++)
#pragma unroll
                for (int nt = 0; nt < 4; nt++)
                    MMA(acc[mt][nt], ahi[mt], blo[nt]);
        }
        buf++; if (buf >= STAGES) buf = 0;
    }

    // ---------------- epilogue ----------------
#pragma unroll
    for (int nt = 0; nt < 4; nt++) {
        int gCol = nBase + wn * 32 + nt * 8 + (lane & 3) * 2;
        float2 bv = make_float2(0.f, 0.f);
        if (mode == 0) bv = *(const float2*)(bias + gCol);
#pragma unroll
        for (int mt = 0; mt < 4; mt++) {
            int gRow = aRow0 + wm * 64 + mt * 16 + (lane >> 2);
            if (mode == 1) {
                *(float2*)(outF + (size_t)gRow * F_ + gCol) =
                    make_float2(acc[mt][nt][0], acc[mt][nt][1]);
                *(float2*)(outF + (size_t)(gRow + 8) * F_ + gCol) =
                    make_float2(acc[mt][nt][2], acc[mt][nt][3]);
            } else {
#pragma unroll
                for (int h = 0; h < 2; h++) {
                    float h0 = acc[mt][nt][h * 2]     + bv.x;
                    float h1 = acc[mt][nt][h * 2 + 1] + bv.y;
                    __nv_bfloat16 hi0 = __float2bfloat16(h0);
                    __nv_bfloat16 hi1 = __float2bfloat16(h1);
                    __nv_bfloat162 vh; vh.x = hi0; vh.y = hi1;
                    __nv_bfloat162 vl;
                    vl.x = __float2bfloat16(h0 - __bfloat162float(hi0));
                    vl.y = __float2bfloat16(h1 - __bfloat162float(hi1));
                    size_t o = (size_t)(gRow + h * 8) * F_ + gCol;
                    *(__nv_bfloat162*)(hHi + o) = vh;
                    *(__nv_bfloat162*)(hLo + o) = vl;
                }
            }
        }
    }
}

// ---------------- prep: split fp32 -> bf16 hi/lo ------------------------------
__global__ __launch_bounds__(256) void split_f32(const float* __restrict__ x,
                                                 __nv_bfloat16* __restrict__ hi,
                                                 __nv_bfloat16* __restrict__ lo) {
    size_t i = (size_t)blockIdx.x * 256 + threadIdx.x;   // one float4 each
    float4 v = ((const float4*)x)[i];
    __nv_bfloat16 h0 = __float2bfloat16(v.x), h1 = __float2bfloat16(v.y);
    __nv_bfloat16 h2 = __float2bfloat16(v.z), h3 = __float2bfloat16(v.w);
    __nv_bfloat162* ph = (__nv_bfloat162*)(hi + i * 4);
    __nv_bfloat162* pl = (__nv_bfloat162*)(lo + i * 4);
    __nv_bfloat162 a, b, c, d;
    a.x = h0; a.y = h1; b.x = h2; b.y = h3;
    c.x = __float2bfloat16(v.x - __bfloat162float(h0));
    c.y = __float2bfloat16(v.y - __bfloat162float(h1));
    d.x = __float2bfloat16(v.z - __bfloat162float(h2));
    d.y = __float2bfloat16(v.w - __bfloat162float(h3));
    ph[0] = a; ph[1] = b; pl[0] = c; pl[1] = d;
}

// ---------------- s/d per node from split hidden ------------------------------
__global__ __launch_bounds__(128) void sd_kernel(
    const __nv_bfloat16* __restrict__ hHi, const __nv_bfloat16* __restrict__ hLo,
    const float* __restrict__ a_src, const float* __restrict__ a_dst,
    float* __restrict__ s, float* __restrict__ d)
{
    int row = blockIdx.x;
    int t = threadIdx.x;                         // 4 cols per thread
    const __nv_bfloat162* ph = (const __nv_bfloat162*)(hHi + (size_t)row * F_) + t * 2;
    const __nv_bfloat162* pl = (const __nv_bfloat162*)(hLo + (size_t)row * F_) + t * 2;
    __nv_bfloat162 h0 = ph[0], h1 = ph[1], l0 = pl[0], l1 = pl[1];
    float4 av = ((const float4*)a_src)[t];
    float4 dv = ((const float4*)a_dst)[t];
    float hv0 = __bfloat162float(h0.x) + __bfloat162float(l0.x);
    float hv1 = __bfloat162float(h0.y) + __bfloat162float(l0.y);
    float hv2 = __bfloat162float(h1.x) + __bfloat162float(l1.x);
    float hv3 = __bfloat162float(h1.y) + __bfloat162float(l1.y);
    float ss = hv0 * av.x + hv1 * av.y + hv2 * av.z + hv3 * av.w;
    float dd = hv0 * dv.x + hv1 * dv.y + hv2 * dv.z + hv3 * dv.w;
#pragma unroll
    for (int o = 16; o; o >>= 1) {
        ss += __shfl_xor_sync(FULLM, ss, o);
        dd += __shfl_xor_sync(FULLM, dd, o);
    }
    __shared__ float rs[4], rd[4];
    int lane = t & 31, wid = t >> 5;
    if (lane == 0) { rs[wid] = ss; rd[wid] = dd; }
    __syncthreads();
    if (t == 0) {
        s[row] = rs[0] + rs[1] + rs[2] + rs[3];
        d[row] = rd[0] + rd[1] + rd[2] + rd[3];
    }
}

// ---------------- softmax probabilities -> split bf16 -------------------------
__global__ __launch_bounds__(256) void prob_kernel(
    const int* __restrict__ adj, const float* __restrict__ s,
    const float* __restrict__ dvec,
    __nv_bfloat16* __restrict__ Phi, __nv_bfloat16* __restrict__ Plo)
{
    int row = blockIdx.x;
    int t = threadIdx.x;
    const int*   arow = adj + (size_t)row * N_;
    const float* drow = dvec + ((row >> 11) << 11);
    float si = s[row];

    float sc[8];
#pragma unroll
    for (int q = 0; q < 8; q++) {
        int j = t + q * 256;
        float x = si + drow[j];
        x = (x >= 0.0f) ? x : SLOPE * x;
        sc[q] = arow[j] ? NEGV : x;
    }
    __shared__ float redA[8], redB[8];
    int lane = t & 31, wid = t >> 5;
    float m = sc[0];
#pragma unroll
    for (int q = 1; q < 8; q++) m = fmaxf(m, sc[q]);
#pragma unroll
    for (int o = 16; o; o >>= 1) m = fmaxf(m, __shfl_xor_sync(FULLM, m, o));
    if (lane == 0) redA[wid] = m;
    __syncthreads();
    if (wid == 0) {
        float v = (lane < 8) ? redA[lane] : -3.4e38f;
#pragma unroll
        for (int o = 16; o; o >>= 1) v = fmaxf(v, __shfl_xor_sync(FULLM, v, o));
        if (lane == 0) redA[0] = v;
    }
    __syncthreads();
    m = redA[0];

    float l = 0.0f;
#pragma unroll
    for (int q = 0; q < 8; q++) { sc[q] = __expf(sc[q] - m); l += sc[q]; }
#pragma unroll
    for (int o = 16; o; o >>= 1) l += __shfl_xor_sync(FULLM, l, o);
    if (lane == 0) redB[wid] = l;
    __syncthreads();
    if (wid == 0) {
        float v = (lane < 8) ? redB[lane] : 0.0f;
#pragma unroll
        for (int o = 16; o; o >>= 1) v += __shfl_xor_sync(FULLM, v, o);
        if (lane == 0) redB[0] = v;
    }
    __syncthreads();
    float inv = 1.0f / redB[0];

    __nv_bfloat16* ph = Phi + (size_t)row * N_;
    __nv_bfloat16* pl = Plo + (size_t)row * N_;
#pragma unroll
    for (int q = 0; q < 8; q++) {
        float p = sc[q] * inv;
        __nv_bfloat16 hi = __float2bfloat16(p);
        ph[t + q * 256] = hi;
        pl[t + q * 256] = __float2bfloat16(p - __bfloat162float(hi));
    }
}

// ---------------- launch -------------------------------------------------------
extern "C" void kernel_launch(void* const* d_in, const int* in_sizes, int n_in,
                              void* d_out, int out_size) {
    (void)in_sizes; (void)n_in; (void)out_size;
    const float* text  = (const float*)d_in[0];
    const int*   adj   = (const int*)d_in[1];
    const float* W     = (const float*)d_in[2];
    const float* bias  = (const float*)d_in[3];
    const float* a_src = (const float*)d_in[4];
    const float* a_dst = (const float*)d_in[5];
    float* out = (float*)d_out;

    __nv_bfloat16 *tHi, *tLo, *WHi, *WLo, *hHi, *hLo, *PHi, *PLo;
    float *sv, *dv;
    cudaGetSymbolAddress((void**)&tHi, g_tHi);
    cudaGetSymbolAddress((void**)&tLo, g_tLo);
    cudaGetSymbolAddress((void**)&WHi, g_WHi);
    cudaGetSymbolAddress((void**)&WLo, g_WLo);
    cudaGetSymbolAddress((void**)&hHi, g_hHi);
    cudaGetSymbolAddress((void**)&hLo, g_hLo);
    cudaGetSymbolAddress((void**)&sv,  g_sv);
    cudaGetSymbolAddress((void**)&dv,  g_dv);
    cudaGetSymbolAddress((void**)&PHi, g_PHi);
    cudaGetSymbolAddress((void**)&PLo, g_PLo);

    static int smem_set = 0;
    if (!smem_set) {
        cudaFuncSetAttribute(gemm_mma, cudaFuncAttributeMaxDynamicSharedMemorySize,
                             SMEM_BYTES);
        smem_set = 1;
    }

    // 0) precision splits
    split_f32<<<(MTOT * F_ / 4) / 256, 256>>>(text, tHi, tLo);
    split_f32<<<(F_ * F_ / 4) / 256, 256>>>(W, WHi, WLo);

    // 1) hidden = text @ W + b   (A: text [16384,512], B: W [512,512])
    gemm_mma<<<dim3(F_ / 128, MTOT / 128, 1), 256, SMEM_BYTES>>>(
        tHi, tLo, WHi, WLo, F_, F_, F_, 0, 0, 0,
        bias, nullptr, hHi, hLo);

    // 2) s, d per node
    sd_kernel<<<MTOT, 128>>>(hHi, hLo, a_src, a_dst, sv, dv);

    // 3) softmax probabilities -> split bf16
    prob_kernel<<<MTOT, 256>>>(adj, sv, dv, PHi, PLo);

    // 4) out = P @ hidden   (A: P [2048,2048] per batch, B: hidden [2048,512])
    gemm_mma<<<dim3(F_ / 128, N_ / 128, B_), 256, SMEM_BYTES>>>(
        PHi, PLo, hHi, hLo, N_, F_, N_, N_, N_, 1,
        nullptr, out, nullptr, nullptr);
}

// round 5
// speedup vs baseline: 1.3048x; 1.3048x over previous
#include <cuda_runtime.h>
#include <cuda_fp16.h>
#include <cstdint>

#define B_    8
#define N_    2048
#define F_    512
#define MTOT  (B_ * N_)          // 16384
#define NEGV  (-10000.0f)
#define SLOPE 0.2f
#define FULLM 0xFFFFFFFFu

// ---------------- device scratch (sanctioned static-array path) -------------
__device__ __half g_tHi[(size_t)MTOT * F_];
__device__ __half g_tLo[(size_t)MTOT * F_];
__device__ __half g_WHi[(size_t)F_ * F_];
__device__ __half g_WLo[(size_t)F_ * F_];
__device__ __half g_hHi[(size_t)MTOT * F_];   // hidden split, row-major
__device__ __half g_hLo[(size_t)MTOT * F_];
__device__ float g_sv[MTOT], g_dv[MTOT];
__device__ __half g_PHi[(size_t)MTOT * N_];
__device__ __half g_PLo[(size_t)MTOT * N_];

// ---------------- base-target PTX helpers ------------------------------------
__device__ __forceinline__ uint32_t smem_u32(const void* p) {
    uint32_t a;
    asm("{ .reg .u64 t; cvta.to.shared.u64 t, %1; cvt.u32.u64 %0, t; }"
        : "=r"(a) : "l"(p));
    return a;
}
__device__ __forceinline__ void cp16(uint32_t dst, const void* src) {
    asm volatile("cp.async.cg.shared.global [%0], [%1], 16;" :: "r"(dst), "l"(src));
}
#define CP_COMMIT() asm volatile("cp.async.commit_group;" ::: "memory")
#define CP_WAIT(n)  asm volatile("cp.async.wait_group %0;" :: "n"(n) : "memory")

#define LDSM4(r0, r1, r2, r3, addr) \
    asm volatile("ldmatrix.sync.aligned.m8n8.x4.shared.b16 {%0,%1,%2,%3}, [%4];" \
                 : "=r"(r0), "=r"(r1), "=r"(r2), "=r"(r3) : "r"(addr))
#define LDSM4T(r0, r1, r2, r3, addr) \
    asm volatile("ldmatrix.sync.aligned.m8n8.x4.trans.shared.b16 {%0,%1,%2,%3}, [%4];" \
                 : "=r"(r0), "=r"(r1), "=r"(r2), "=r"(r3) : "r"(addr))

#define MMA(d, a, b) \
    asm volatile("mma.sync.aligned.m16n8k16.row.col.f32.f16.f16.f32 " \
                 "{%0,%1,%2,%3}, {%4,%5,%6,%7}, {%8,%9}, {%0,%1,%2,%3};" \
                 : "+f"((d)[0]), "+f"((d)[1]), "+f"((d)[2]), "+f"((d)[3]) \
                 : "r"((a)[0]), "r"((a)[1]), "r"((a)[2]), "r"((a)[3]), \
                   "r"((b)[0]), "r"((b)[1]))

// ---------------- SMEM layout -------------------------------------------------
// A tile: 128 rows x 32 f16, pitch 80 B  -> conflict-free ldmatrix
// B tile:  32 rows x 128 f16, pitch 272 B
#define A_PITCH_B 80
#define B_PITCH_B 272
#define SZ_A (128 * A_PITCH_B)            // 10240
#define SZ_B (32 * B_PITCH_B)             // 8704
#define STAGES 3

// ---------------- split-fp16 GEMM (mma.sync), CTA 128x128x32 ------------------
// NTERMS==3: C = Ahi*Bhi + Alo*Bhi + Ahi*Blo   (lo*lo dropped)
// NTERMS==2: C = Ahi*Bhi + Alo*Bhi             (B lo not loaded at all)
// MODE 0: h = C + bias -> split into (hHi, hLo) fp16, row-major
// MODE 1: outF[row][512] = C  (fp32)
template<int NTERMS, int MODE>
__global__ __launch_bounds__(256) void gemm_mma(
    const __half* __restrict__ Ahi, const __half* __restrict__ Alo,
    const __half* __restrict__ Bhi, const __half* __restrict__ Blo,
    int lda, int ldb, int K, int AZ, int BZ,
    const float* __restrict__ bias, float* __restrict__ outF,
    __half* __restrict__ hHi, __half* __restrict__ hLo)
{
    constexpr int NB = (NTERMS == 3) ? 2 : 1;
    constexpr uint32_t BUF_STRIDE = 2 * SZ_A + NB * SZ_B;

    extern __shared__ char sm[];
    const uint32_t smBase = smem_u32(sm);

    const int t = threadIdx.x;
    const int warp = t >> 5, lane = t & 31;
    const int wm = warp & 1, wn = warp >> 1;          // 2 x 4 warp grid

    const int nBase  = blockIdx.x * 128;
    const int aRow0  = blockIdx.y * 128 + blockIdx.z * AZ;
    const int bRow0  = blockIdx.z * BZ;

    float acc[4][4][4];
#pragma unroll
    for (int i = 0; i < 4; i++)
#pragma unroll
        for (int j = 0; j < 4; j++)
#pragma unroll
            for (int q = 0; q < 4; q++) acc[i][j][q] = 0.0f;

    // ---- per-thread load geometry ----
    const int rA = t >> 2, chA = t & 3;               // A rows rA, rA+64
    const int rB = t >> 4, chB = t & 15;              // B rows rB, rB+16
    const __half* pAh = Ahi + (size_t)(aRow0 + rA) * lda + chA * 8;
    const __half* pAl = Alo + (size_t)(aRow0 + rA) * lda + chA * 8;
    const __half* pBh = Bhi + (size_t)(bRow0 + rB) * ldb + nBase + chB * 8;
    const __half* pBl = (NTERMS == 3)
        ? Blo + (size_t)(bRow0 + rB) * ldb + nBase + chB * 8 : nullptr;
    const uint32_t sA = smBase + rA * A_PITCH_B + chA * 16;
    const uint32_t sB = smBase + 2 * SZ_A + rB * B_PITCH_B + chB * 16;
    const size_t a64 = (size_t)64 * lda;
    const size_t b16 = (size_t)16 * ldb;

    auto load_tile = [&](int buf, int kt) {
        const size_t ka = (size_t)kt * 32;
        const size_t kb = (size_t)kt * 32 * ldb;
        const uint32_t ob = buf * BUF_STRIDE;
        cp16(sA + ob,                          pAh + ka);
        cp16(sA + ob + 64 * A_PITCH_B,         pAh + ka + a64);
        cp16(sA + ob + SZ_A,                   pAl + ka);
        cp16(sA + ob + SZ_A + 64 * A_PITCH_B,  pAl + ka + a64);
        cp16(sB + ob,                          pBh + kb);
        cp16(sB + ob + 16 * B_PITCH_B,         pBh + kb + b16);
        if (NTERMS == 3) {
            cp16(sB + ob + SZ_B,                          pBl + kb);
            cp16(sB + ob + SZ_B + 16 * B_PITCH_B,         pBl + kb + b16);
        }
    };

    // per-lane ldmatrix address components
    const int aRowL  = lane & 15;
    const int aColB  = (lane >> 4) * 16;
    const int bRowL  = lane & 15;
    const int bColB  = (wn * 32 + (lane >> 4) * 8) * 2;

    const int ntiles = K / 32;
    load_tile(0, 0); CP_COMMIT();
    load_tile(1, 1); CP_COMMIT();

    int buf = 0;
    for (int kt = 0; kt < ntiles; kt++) {
        if (kt < ntiles - 1) { CP_WAIT(1); } else { CP_WAIT(0); }
        __syncthreads();

        if (kt + 2 < ntiles) {
            int nb = buf + 2; if (nb >= STAGES) nb -= STAGES;
            load_tile(nb, kt + 2);
            CP_COMMIT();
        }

        const uint32_t ob  = smBase + buf * BUF_STRIDE;
        const uint32_t obB = ob + 2 * SZ_A;

#pragma unroll
        for (int ks = 0; ks < 2; ks++) {
            uint32_t ahi[4][4], alo[4][4];
#pragma unroll
            for (int mt = 0; mt < 4; mt++) {
                uint32_t ra = ob + (wm * 64 + mt * 16 + aRowL) * A_PITCH_B
                            + ks * 32 + aColB;
                LDSM4(ahi[mt][0], ahi[mt][1], ahi[mt][2], ahi[mt][3], ra);
                LDSM4(alo[mt][0], alo[mt][1], alo[mt][2], alo[mt][3], ra + SZ_A);
            }
            uint32_t bhi[4][2];
#pragma unroll
            for (int bt = 0; bt < 2; bt++) {
                uint32_t rb = obB + (ks * 16 + bRowL) * B_PITCH_B + bColB + bt * 32;
                LDSM4T(bhi[bt*2][0], bhi[bt*2][1], bhi[bt*2+1][0], bhi[bt*2+1][1], rb);
            }
#pragma unroll
            for (int mt = 0; mt < 4; mt++)
#pragma unroll
                for (int nt = 0; nt < 4; nt++)
                    MMA(acc[mt][nt], ahi[mt], bhi[nt]);
#pragma unroll
            for (int mt = 0; mt < 4; mt++)
#pragma unroll
                for (int nt = 0; nt < 4; nt++)
                    MMA(acc[mt][nt], alo[mt], bhi[nt]);

            if (NTERMS == 3) {
                uint32_t blo[4][2];
#pragma unroll
                for (int bt = 0; bt < 2; bt++) {
                    uint32_t rb = obB + SZ_B + (ks * 16 + bRowL) * B_PITCH_B
                                + bColB + bt * 32;
                    LDSM4T(blo[bt*2][0], blo[bt*2][1], blo[bt*2+1][0],
                           blo[bt*2+1][1], rb);
                }
#pragma unroll
                for (int mt = 0; mt < 4; mt++)
#pragma unroll
                    for (int nt = 0; nt < 4; nt++)
                        MMA(acc[mt][nt], ahi[mt], blo[nt]);
            }
        }
        buf++; if (buf >= STAGES) buf = 0;
    }

    // ---------------- epilogue ----------------
#pragma unroll
    for (int nt = 0; nt < 4; nt++) {
        int gCol = nBase + wn * 32 + nt * 8 + (lane & 3) * 2;
        float2 bv = make_float2(0.f, 0.f);
        if (MODE == 0) bv = *(const float2*)(bias + gCol);
#pragma unroll
        for (int mt = 0; mt < 4; mt++) {
            int gRow = aRow0 + wm * 64 + mt * 16 + (lane >> 2);
            if (MODE == 1) {
                *(float2*)(outF + (size_t)gRow * F_ + gCol) =
                    make_float2(acc[mt][nt][0], acc[mt][nt][1]);
                *(float2*)(outF + (size_t)(gRow + 8) * F_ + gCol) =
                    make_float2(acc[mt][nt][2], acc[mt][nt][3]);
            } else {
#pragma unroll
                for (int h = 0; h < 2; h++) {
                    float h0 = acc[mt][nt][h * 2]     + bv.x;
                    float h1 = acc[mt][nt][h * 2 + 1] + bv.y;
                    __half hi0 = __float2half_rn(h0);
                    __half hi1 = __float2half_rn(h1);
                    __half2 vh; vh.x = hi0; vh.y = hi1;
                    __half2 vl;
                    vl.x = __float2half_rn(h0 - __half2float(hi0));
                    vl.y = __float2half_rn(h1 - __half2float(hi1));
                    size_t o = (size_t)(gRow + h * 8) * F_ + gCol;
                    *(__half2*)(hHi + o) = vh;
                    *(__half2*)(hLo + o) = vl;
                }
            }
        }
    }
}

// ---------------- prep: split fp32 -> fp16 hi/lo ------------------------------
__global__ __launch_bounds__(256) void split_f32(const float* __restrict__ x,
                                                 __half* __restrict__ hi,
                                                 __half* __restrict__ lo) {
    size_t i = (size_t)blockIdx.x * 256 + threadIdx.x;   // one float4 each
    float4 v = ((const float4*)x)[i];
    __half h0 = __float2half_rn(v.x), h1 = __float2half_rn(v.y);
    __half h2 = __float2half_rn(v.z), h3 = __float2half_rn(v.w);
    __half2* ph = (__half2*)(hi + i * 4);
    __half2* pl = (__half2*)(lo + i * 4);
    __half2 a, b, c, d;
    a.x = h0; a.y = h1; b.x = h2; b.y = h3;
    c.x = __float2half_rn(v.x - __half2float(h0));
    c.y = __float2half_rn(v.y - __half2float(h1));
    d.x = __float2half_rn(v.z - __half2float(h2));
    d.y = __float2half_rn(v.w - __half2float(h3));
    ph[0] = a; ph[1] = b; pl[0] = c; pl[1] = d;
}

// ---------------- s/d per node from split hidden ------------------------------
__global__ __launch_bounds__(128) void sd_kernel(
    const __half* __restrict__ hHi, const __half* __restrict__ hLo,
    const float* __restrict__ a_src, const float* __restrict__ a_dst,
    float* __restrict__ s, float* __restrict__ d)
{
    int row = blockIdx.x;
    int t = threadIdx.x;                         // 4 cols per thread
    const __half2* ph = (const __half2*)(hHi + (size_t)row * F_) + t * 2;
    const __half2* pl = (const __half2*)(hLo + (size_t)row * F_) + t * 2;
    __half2 h0 = ph[0], h1 = ph[1], l0 = pl[0], l1 = pl[1];
    float4 av = ((const float4*)a_src)[t];
    float4 dv = ((const float4*)a_dst)[t];
    float hv0 = __half2float(h0.x) + __half2float(l0.x);
    float hv1 = __half2float(h0.y) + __half2float(l0.y);
    float hv2 = __half2float(h1.x) + __half2float(l1.x);
    float hv3 = __half2float(h1.y) + __half2float(l1.y);
    float ss = hv0 * av.x + hv1 * av.y + hv2 * av.z + hv3 * av.w;
    float dd = hv0 * dv.x + hv1 * dv.y + hv2 * dv.z + hv3 * dv.w;
#pragma unroll
    for (int o = 16; o; o >>= 1) {
        ss += __shfl_xor_sync(FULLM, ss, o);
        dd += __shfl_xor_sync(FULLM, dd, o);
    }
    __shared__ float rs[4], rd[4];
    int lane = t & 31, wid = t >> 5;
    if (lane == 0) { rs[wid] = ss; rd[wid] = dd; }
    __syncthreads();
    if (t == 0) {
        s[row] = rs[0] + rs[1] + rs[2] + rs[3];
        d[row] = rd[0] + rd[1] + rd[2] + rd[3];
    }
}

// ---------------- softmax probabilities -> split fp16 -------------------------
__global__ __launch_bounds__(256) void prob_kernel(
    const int* __restrict__ adj, const float* __restrict__ s,
    const float* __restrict__ dvec,
    __half* __restrict__ Phi, __half* __restrict__ Plo)
{
    int row = blockIdx.x;
    int t = threadIdx.x;
    const int*   arow = adj + (size_t)row * N_;
    const float* drow = dvec + ((row >> 11) << 11);
    float si = s[row];

    float sc[8];
#pragma unroll
    for (int q = 0; q < 8; q++) {
        int j = t + q * 256;
        float x = si + drow[j];
        x = (x >= 0.0f) ? x : SLOPE * x;
        sc[q] = arow[j] ? NEGV : x;
    }
    __shared__ float redA[8], redB[8];
    int lane = t & 31, wid = t >> 5;
    float m = sc[0];
#pragma unroll
    for (int q = 1; q < 8; q++) m = fmaxf(m, sc[q]);
#pragma unroll
    for (int o = 16; o; o >>= 1) m = fmaxf(m, __shfl_xor_sync(FULLM, m, o));
    if (lane == 0) redA[wid] = m;
    __syncthreads();
    if (wid == 0) {
        float v = (lane < 8) ? redA[lane] : -3.4e38f;
#pragma unroll
        for (int o = 16; o; o >>= 1) v = fmaxf(v, __shfl_xor_sync(FULLM, v, o));
        if (lane == 0) redA[0] = v;
    }
    __syncthreads();
    m = redA[0];

    float l = 0.0f;
#pragma unroll
    for (int q = 0; q < 8; q++) { sc[q] = __expf(sc[q] - m); l += sc[q]; }
#pragma unroll
    for (int o = 16; o; o >>= 1) l += __shfl_xor_sync(FULLM, l, o);
    if (lane == 0) redB[wid] = l;
    __syncthreads();
    if (wid == 0) {
        float v = (lane < 8) ? redB[lane] : 0.0f;
#pragma unroll
        for (int o = 16; o; o >>= 1) v += __shfl_xor_sync(FULLM, v, o);
        if (lane == 0) redB[0] = v;
    }
    __syncthreads();
    float inv = 1.0f / redB[0];

    __half* ph = Phi + (size_t)row * N_;
    __half* pl = Plo + (size_t)row * N_;
#pragma unroll
    for (int q = 0; q < 8; q++) {
        float p = sc[q] * inv;
        __half hi = __float2half_rn(p);
        ph[t + q * 256] = hi;
        pl[t + q * 256] = __float2half_rn(p - __half2float(hi));
    }
}

// ---------------- launch -------------------------------------------------------
extern "C" void kernel_launch(void* const* d_in, const int* in_sizes, int n_in,
                              void* d_out, int out_size) {
    (void)in_sizes; (void)n_in; (void)out_size;
    const float* text  = (const float*)d_in[0];
    const int*   adj   = (const int*)d_in[1];
    const float* W     = (const float*)d_in[2];
    const float* bias  = (const float*)d_in[3];
    const float* a_src = (const float*)d_in[4];
    const float* a_dst = (const float*)d_in[5];
    float* out = (float*)d_out;

    __half *tHi, *tLo, *WHi, *WLo, *hHi, *hLo, *PHi, *PLo;
    float *sv, *dv;
    cudaGetSymbolAddress((void**)&tHi, g_tHi);
    cudaGetSymbolAddress((void**)&tLo, g_tLo);
    cudaGetSymbolAddress((void**)&WHi, g_WHi);
    cudaGetSymbolAddress((void**)&WLo, g_WLo);
    cudaGetSymbolAddress((void**)&hHi, g_hHi);
    cudaGetSymbolAddress((void**)&hLo, g_hLo);
    cudaGetSymbolAddress((void**)&sv,  g_sv);
    cudaGetSymbolAddress((void**)&dv,  g_dv);
    cudaGetSymbolAddress((void**)&PHi, g_PHi);
    cudaGetSymbolAddress((void**)&PLo, g_PLo);

    constexpr int SMEM3 = STAGES * (2 * SZ_A + 2 * SZ_B);   // 113664
    constexpr int SMEM2 = STAGES * (2 * SZ_A + 1 * SZ_B);   // 87552

    static int smem_set = 0;
    if (!smem_set) {
        cudaFuncSetAttribute(gemm_mma<3, 0>,
                             cudaFuncAttributeMaxDynamicSharedMemorySize, SMEM3);
        cudaFuncSetAttribute(gemm_mma<2, 1>,
                             cudaFuncAttributeMaxDynamicSharedMemorySize, SMEM2);
        smem_set = 1;
    }

    // 0) precision splits
    split_f32<<<(MTOT * F_ / 4) / 256, 256>>>(text, tHi, tLo);
    split_f32<<<(F_ * F_ / 4) / 256, 256>>>(W, WHi, WLo);

    // 1) hidden = text @ W + b   (3-term fp16: hidden accurate to ~1e-6)
    gemm_mma<3, 0><<<dim3(F_ / 128, MTOT / 128, 1), 256, SMEM3>>>(
        tHi, tLo, WHi, WLo, F_, F_, F_, 0, 0,
        bias, nullptr, hHi, hLo);

    // 2) s, d per node
    sd_kernel<<<MTOT, 128>>>(hHi, hLo, a_src, a_dst, sv, dv);

    // 3) softmax probabilities -> split fp16
    prob_kernel<<<MTOT, 256>>>(adj, sv, dv, PHi, PLo);

    // 4) out = P @ hidden   (2-term fp16: Phi*Hhi + Plo*Hhi)
    gemm_mma<2, 1><<<dim3(F_ / 128, N_ / 128, B_), 256, SMEM2>>>(
        PHi, PLo, hHi, nullptr, N_, F_, N_, N_, N_,
        nullptr, out, nullptr, nullptr);
}

// round 6
// speedup vs baseline: 1.8469x; 1.4155x over previous
#include <cuda_runtime.h>
#include <cuda_fp16.h>
#include <cstdint>

#define B_    8
#define N_    2048
#define F_    512
#define MTOT  (B_ * N_)          // 16384
#define NEGV  (-10000.0f)
#define SLOPE 0.2f
#define FULLM 0xFFFFFFFFu

// ---------------- device scratch (sanctioned static-array path) -------------
__device__ __half g_tHi[(size_t)MTOT * F_];
__device__ __half g_tLo[(size_t)MTOT * F_];
__device__ __half g_WHi[(size_t)F_ * F_];
__device__ __half g_WLo[(size_t)F_ * F_];
__device__ __half g_hHi[(size_t)MTOT * F_];   // hidden split, row-major
__device__ __half g_hLo[(size_t)MTOT * F_];
__device__ float g_sv[MTOT], g_dv[MTOT];
__device__ __half g_PHi[(size_t)MTOT * N_];

// ---------------- base-target PTX helpers ------------------------------------
__device__ __forceinline__ uint32_t smem_u32(const void* p) {
    uint32_t a;
    asm("{ .reg .u64 t; cvta.to.shared.u64 t, %1; cvt.u32.u64 %0, t; }"
        : "=r"(a) : "l"(p));
    return a;
}
__device__ __forceinline__ void cp16(uint32_t dst, const void* src) {
    asm volatile("cp.async.cg.shared.global [%0], [%1], 16;" :: "r"(dst), "l"(src));
}
#define CP_COMMIT() asm volatile("cp.async.commit_group;" ::: "memory")
#define CP_WAIT(n)  asm volatile("cp.async.wait_group %0;" :: "n"(n) : "memory")

#define LDSM4(r0, r1, r2, r3, addr) \
    asm volatile("ldmatrix.sync.aligned.m8n8.x4.shared.b16 {%0,%1,%2,%3}, [%4];" \
                 : "=r"(r0), "=r"(r1), "=r"(r2), "=r"(r3) : "r"(addr))
#define LDSM4T(r0, r1, r2, r3, addr) \
    asm volatile("ldmatrix.sync.aligned.m8n8.x4.trans.shared.b16 {%0,%1,%2,%3}, [%4];" \
                 : "=r"(r0), "=r"(r1), "=r"(r2), "=r"(r3) : "r"(addr))

#define MMA(d, a, b) \
    asm volatile("mma.sync.aligned.m16n8k16.row.col.f32.f16.f16.f32 " \
                 "{%0,%1,%2,%3}, {%4,%5,%6,%7}, {%8,%9}, {%0,%1,%2,%3};" \
                 : "+f"((d)[0]), "+f"((d)[1]), "+f"((d)[2]), "+f"((d)[3]) \
                 : "r"((a)[0]), "r"((a)[1]), "r"((a)[2]), "r"((a)[3]), \
                   "r"((b)[0]), "r"((b)[1]))

// ---------------- SMEM layout -------------------------------------------------
#define A_PITCH_B 80
#define B_PITCH_B 272
#define SZ_A (128 * A_PITCH_B)            // 10240
#define SZ_B (32 * B_PITCH_B)             // 8704
#define STAGES 3

// ---------------- split-fp16 GEMM (mma.sync), CTA 128x128x32 ------------------
// NTERMS==3: C = Ahi*Bhi + Alo*Bhi + Ahi*Blo
// NTERMS==1: C = Ahi*Bhi              (lo tiles never loaded)
// MODE 0: h = C + bias -> split into (hHi, hLo) fp16, row-major
// MODE 1: outF[row][512] = C  (fp32)
template<int NTERMS, int MODE>
__global__ __launch_bounds__(256) void gemm_mma(
    const __half* __restrict__ Ahi, const __half* __restrict__ Alo,
    const __half* __restrict__ Bhi, const __half* __restrict__ Blo,
    int lda, int ldb, int K, int AZ, int BZ,
    const float* __restrict__ bias, float* __restrict__ outF,
    __half* __restrict__ hHi, __half* __restrict__ hLo)
{
    constexpr int NA = (NTERMS == 3) ? 2 : 1;
    constexpr int NB = (NTERMS == 3) ? 2 : 1;
    constexpr uint32_t BUF_STRIDE = NA * SZ_A + NB * SZ_B;

    extern __shared__ char sm[];
    const uint32_t smBase = smem_u32(sm);

    const int t = threadIdx.x;
    const int warp = t >> 5, lane = t & 31;
    const int wm = warp & 1, wn = warp >> 1;          // 2 x 4 warp grid

    const int nBase  = blockIdx.x * 128;
    const int aRow0  = blockIdx.y * 128 + blockIdx.z * AZ;
    const int bRow0  = blockIdx.z * BZ;

    float acc[4][4][4];
#pragma unroll
    for (int i = 0; i < 4; i++)
#pragma unroll
        for (int j = 0; j < 4; j++)
#pragma unroll
            for (int q = 0; q < 4; q++) acc[i][j][q] = 0.0f;

    // ---- per-thread load geometry ----
    const int rA = t >> 2, chA = t & 3;               // A rows rA, rA+64
    const int rB = t >> 4, chB = t & 15;              // B rows rB, rB+16
    const __half* pAh = Ahi + (size_t)(aRow0 + rA) * lda + chA * 8;
    const __half* pAl = (NA == 2)
        ? Alo + (size_t)(aRow0 + rA) * lda + chA * 8 : nullptr;
    const __half* pBh = Bhi + (size_t)(bRow0 + rB) * ldb + nBase + chB * 8;
    const __half* pBl = (NB == 2)
        ? Blo + (size_t)(bRow0 + rB) * ldb + nBase + chB * 8 : nullptr;
    const uint32_t sA = smBase + rA * A_PITCH_B + chA * 16;
    const uint32_t sB = smBase + NA * SZ_A + rB * B_PITCH_B + chB * 16;
    const size_t a64 = (size_t)64 * lda;
    const size_t b16 = (size_t)16 * ldb;

    auto load_tile = [&](int buf, int kt) {
        const size_t ka = (size_t)kt * 32;
        const size_t kb = (size_t)kt * 32 * ldb;
        const uint32_t ob = buf * BUF_STRIDE;
        cp16(sA + ob,                          pAh + ka);
        cp16(sA + ob + 64 * A_PITCH_B,         pAh + ka + a64);
        if (NA == 2) {
            cp16(sA + ob + SZ_A,                   pAl + ka);
            cp16(sA + ob + SZ_A + 64 * A_PITCH_B,  pAl + ka + a64);
        }
        cp16(sB + ob,                          pBh + kb);
        cp16(sB + ob + 16 * B_PITCH_B,         pBh + kb + b16);
        if (NB == 2) {
            cp16(sB + ob + SZ_B,                   pBl + kb);
            cp16(sB + ob + SZ_B + 16 * B_PITCH_B,  pBl + kb + b16);
        }
    };

    // per-lane ldmatrix address components
    const int aRowL  = lane & 15;
    const int aColB  = (lane >> 4) * 16;
    const int bRowL  = lane & 15;
    const int bColB  = (wn * 32 + (lane >> 4) * 8) * 2;

    const int ntiles = K / 32;
    load_tile(0, 0); CP_COMMIT();
    load_tile(1, 1); CP_COMMIT();

    int buf = 0;
    for (int kt = 0; kt < ntiles; kt++) {
        if (kt < ntiles - 1) { CP_WAIT(1); } else { CP_WAIT(0); }
        __syncthreads();

        if (kt + 2 < ntiles) {
            int nb = buf + 2; if (nb >= STAGES) nb -= STAGES;
            load_tile(nb, kt + 2);
            CP_COMMIT();
        }

        const uint32_t ob  = smBase + buf * BUF_STRIDE;
        const uint32_t obB = ob + NA * SZ_A;

#pragma unroll
        for (int ks = 0; ks < 2; ks++) {
            uint32_t ahi[4][4];
#pragma unroll
            for (int mt = 0; mt < 4; mt++) {
                uint32_t ra = ob + (wm * 64 + mt * 16 + aRowL) * A_PITCH_B
                            + ks * 32 + aColB;
                LDSM4(ahi[mt][0], ahi[mt][1], ahi[mt][2], ahi[mt][3], ra);
            }
            uint32_t bhi[4][2];
#pragma unroll
            for (int bt = 0; bt < 2; bt++) {
                uint32_t rb = obB + (ks * 16 + bRowL) * B_PITCH_B + bColB + bt * 32;
                LDSM4T(bhi[bt*2][0], bhi[bt*2][1], bhi[bt*2+1][0], bhi[bt*2+1][1], rb);
            }
#pragma unroll
            for (int mt = 0; mt < 4; mt++)
#pragma unroll
                for (int nt = 0; nt < 4; nt++)
                    MMA(acc[mt][nt], ahi[mt], bhi[nt]);

            if (NA == 2) {
                uint32_t alo[4][4];
#pragma unroll
                for (int mt = 0; mt < 4; mt++) {
                    uint32_t ra = ob + SZ_A + (wm * 64 + mt * 16 + aRowL) * A_PITCH_B
                                + ks * 32 + aColB;
                    LDSM4(alo[mt][0], alo[mt][1], alo[mt][2], alo[mt][3], ra);
                }
#pragma unroll
                for (int mt = 0; mt < 4; mt++)
#pragma unroll
                    for (int nt = 0; nt < 4; nt++)
                        MMA(acc[mt][nt], alo[mt], bhi[nt]);
            }
            if (NB == 2) {
                uint32_t blo[4][2];
#pragma unroll
                for (int bt = 0; bt < 2; bt++) {
                    uint32_t rb = obB + SZ_B + (ks * 16 + bRowL) * B_PITCH_B
                                + bColB + bt * 32;
                    LDSM4T(blo[bt*2][0], blo[bt*2][1], blo[bt*2+1][0],
                           blo[bt*2+1][1], rb);
                }
#pragma unroll
                for (int mt = 0; mt < 4; mt++)
#pragma unroll
                    for (int nt = 0; nt < 4; nt++)
                        MMA(acc[mt][nt], ahi[mt], blo[nt]);
            }
        }
        buf++; if (buf >= STAGES) buf = 0;
    }

    // ---------------- epilogue ----------------
#pragma unroll
    for (int nt = 0; nt < 4; nt++) {
        int gCol = nBase + wn * 32 + nt * 8 + (lane & 3) * 2;
        float2 bv = make_float2(0.f, 0.f);
        if (MODE == 0) bv = *(const float2*)(bias + gCol);
#pragma unroll
        for (int mt = 0; mt < 4; mt++) {
            int gRow = aRow0 + wm * 64 + mt * 16 + (lane >> 2);
            if (MODE == 1) {
                *(float2*)(outF + (size_t)gRow * F_ + gCol) =
                    make_float2(acc[mt][nt][0], acc[mt][nt][1]);
                *(float2*)(outF + (size_t)(gRow + 8) * F_ + gCol) =
                    make_float2(acc[mt][nt][2], acc[mt][nt][3]);
            } else {
#pragma unroll
                for (int h = 0; h < 2; h++) {
                    float h0 = acc[mt][nt][h * 2]     + bv.x;
                    float h1 = acc[mt][nt][h * 2 + 1] + bv.y;
                    __half hi0 = __float2half_rn(h0);
                    __half hi1 = __float2half_rn(h1);
                    __half2 vh; vh.x = hi0; vh.y = hi1;
                    __half2 vl;
                    vl.x = __float2half_rn(h0 - __half2float(hi0));
                    vl.y = __float2half_rn(h1 - __half2float(hi1));
                    size_t o = (size_t)(gRow + h * 8) * F_ + gCol;
                    *(__half2*)(hHi + o) = vh;
                    *(__half2*)(hLo + o) = vl;
                }
            }
        }
    }
}

// ---------------- prep: split fp32 -> fp16 hi/lo ------------------------------
__global__ __launch_bounds__(256) void split_f32(const float* __restrict__ x,
                                                 __half* __restrict__ hi,
                                                 __half* __restrict__ lo) {
    size_t i = (size_t)blockIdx.x * 256 + threadIdx.x;   // one float4 each
    float4 v = ((const float4*)x)[i];
    __half h0 = __float2half_rn(v.x), h1 = __float2half_rn(v.y);
    __half h2 = __float2half_rn(v.z), h3 = __float2half_rn(v.w);
    __half2* ph = (__half2*)(hi + i * 4);
    __half2* pl = (__half2*)(lo + i * 4);
    __half2 a, b, c, d;
    a.x = h0; a.y = h1; b.x = h2; b.y = h3;
    c.x = __float2half_rn(v.x - __half2float(h0));
    c.y = __float2half_rn(v.y - __half2float(h1));
    d.x = __float2half_rn(v.z - __half2float(h2));
    d.y = __float2half_rn(v.w - __half2float(h3));
    ph[0] = a; ph[1] = b; pl[0] = c; pl[1] = d;
}

// ---------------- s/d per node from split hidden ------------------------------
__global__ __launch_bounds__(128) void sd_kernel(
    const __half* __restrict__ hHi, const __half* __restrict__ hLo,
    const float* __restrict__ a_src, const float* __restrict__ a_dst,
    float* __restrict__ s, float* __restrict__ d)
{
    int row = blockIdx.x;
    int t = threadIdx.x;                         // 4 cols per thread
    const __half2* ph = (const __half2*)(hHi + (size_t)row * F_) + t * 2;
    const __half2* pl = (const __half2*)(hLo + (size_t)row * F_) + t * 2;
    __half2 h0 = ph[0], h1 = ph[1], l0 = pl[0], l1 = pl[1];
    float4 av = ((const float4*)a_src)[t];
    float4 dv = ((const float4*)a_dst)[t];
    float hv0 = __half2float(h0.x) + __half2float(l0.x);
    float hv1 = __half2float(h0.y) + __half2float(l0.y);
    float hv2 = __half2float(h1.x) + __half2float(l1.x);
    float hv3 = __half2float(h1.y) + __half2float(l1.y);
    float ss = hv0 * av.x + hv1 * av.y + hv2 * av.z + hv3 * av.w;
    float dd = hv0 * dv.x + hv1 * dv.y + hv2 * dv.z + hv3 * dv.w;
#pragma unroll
    for (int o = 16; o; o >>= 1) {
        ss += __shfl_xor_sync(FULLM, ss, o);
        dd += __shfl_xor_sync(FULLM, dd, o);
    }
    __shared__ float rs[4], rd[4];
    int lane = t & 31, wid = t >> 5;
    if (lane == 0) { rs[wid] = ss; rd[wid] = dd; }
    __syncthreads();
    if (t == 0) {
        s[row] = rs[0] + rs[1] + rs[2] + rs[3];
        d[row] = rd[0] + rd[1] + rd[2] + rd[3];
    }
}

// ---------------- softmax probabilities -> fp16 (hi only) ---------------------
// Vectorized: each thread owns 8 consecutive js -> int4 adj loads, uint4 store.
__global__ __launch_bounds__(256) void prob_kernel(
    const int* __restrict__ adj, const float* __restrict__ s,
    const float* __restrict__ dvec, __half* __restrict__ Phi)
{
    int row = blockIdx.x;
    int t = threadIdx.x;
    const int j0 = t * 8;
    const int4* arow = (const int4*)(adj + (size_t)row * N_ + j0);
    const float4* drow = (const float4*)(dvec + ((row >> 11) << 11) + j0);
    float si = s[row];

    int4 a0 = arow[0], a1 = arow[1];
    float4 d0 = drow[0], d1 = drow[1];
    int am[8] = {a0.x, a0.y, a0.z, a0.w, a1.x, a1.y, a1.z, a1.w};
    float dv[8] = {d0.x, d0.y, d0.z, d0.w, d1.x, d1.y, d1.z, d1.w};

    float sc[8];
#pragma unroll
    for (int q = 0; q < 8; q++) {
        float x = si + dv[q];
        x = (x >= 0.0f) ? x : SLOPE * x;
        sc[q] = am[q] ? NEGV : x;
    }

    __shared__ float redA[8], redB[8];
    int lane = t & 31, wid = t >> 5;
    float m = sc[0];
#pragma unroll
    for (int q = 1; q < 8; q++) m = fmaxf(m, sc[q]);
#pragma unroll
    for (int o = 16; o; o >>= 1) m = fmaxf(m, __shfl_xor_sync(FULLM, m, o));
    if (lane == 0) redA[wid] = m;
    __syncthreads();
    if (wid == 0) {
        float v = (lane < 8) ? redA[lane] : -3.4e38f;
#pragma unroll
        for (int o = 16; o; o >>= 1) v = fmaxf(v, __shfl_xor_sync(FULLM, v, o));
        if (lane == 0) redA[0] = v;
    }
    __syncthreads();
    m = redA[0];

    float l = 0.0f;
#pragma unroll
    for (int q = 0; q < 8; q++) { sc[q] = __expf(sc[q] - m); l += sc[q]; }
#pragma unroll
    for (int o = 16; o; o >>= 1) l += __shfl_xor_sync(FULLM, l, o);
    if (lane == 0) redB[wid] = l;
    __syncthreads();
    if (wid == 0) {
        float v = (lane < 8) ? redB[lane] : 0.0f;
#pragma unroll
        for (int o = 16; o; o >>= 1) v += __shfl_xor_sync(FULLM, v, o);
        if (lane == 0) redB[0] = v;
    }
    __syncthreads();
    float inv = 1.0f / redB[0];

    __half2 w[4];
#pragma unroll
    for (int q = 0; q < 4; q++) {
        w[q].x = __float2half_rn(sc[q * 2] * inv);
        w[q].y = __float2half_rn(sc[q * 2 + 1] * inv);
    }
    *(uint4*)(Phi + (size_t)row * N_ + j0) = *(uint4*)w;
}

// ---------------- launch -------------------------------------------------------
extern "C" void kernel_launch(void* const* d_in, const int* in_sizes, int n_in,
                              void* d_out, int out_size) {
    (void)in_sizes; (void)n_in; (void)out_size;
    const float* text  = (const float*)d_in[0];
    const int*   adj   = (const int*)d_in[1];
    const float* W     = (const float*)d_in[2];
    const float* bias  = (const float*)d_in[3];
    const float* a_src = (const float*)d_in[4];
    const float* a_dst = (const float*)d_in[5];
    float* out = (float*)d_out;

    __half *tHi, *tLo, *WHi, *WLo, *hHi, *hLo, *PHi;
    float *sv, *dv;
    cudaGetSymbolAddress((void**)&tHi, g_tHi);
    cudaGetSymbolAddress((void**)&tLo, g_tLo);
    cudaGetSymbolAddress((void**)&WHi, g_WHi);
    cudaGetSymbolAddress((void**)&WLo, g_WLo);
    cudaGetSymbolAddress((void**)&hHi, g_hHi);
    cudaGetSymbolAddress((void**)&hLo, g_hLo);
    cudaGetSymbolAddress((void**)&sv,  g_sv);
    cudaGetSymbolAddress((void**)&dv,  g_dv);
    cudaGetSymbolAddress((void**)&PHi, g_PHi);

    constexpr int SMEM3 = STAGES * (2 * SZ_A + 2 * SZ_B);   // 113664
    constexpr int SMEM1 = STAGES * (1 * SZ_A + 1 * SZ_B);   // 56832

    static int smem_set = 0;
    if (!smem_set) {
        cudaFuncSetAttribute(gemm_mma<3, 0>,
                             cudaFuncAttributeMaxDynamicSharedMemorySize, SMEM3);
        cudaFuncSetAttribute(gemm_mma<1, 1>,
                             cudaFuncAttributeMaxDynamicSharedMemorySize, SMEM1);
        smem_set = 1;
    }

    // 0) precision splits
    split_f32<<<(MTOT * F_ / 4) / 256, 256>>>(text, tHi, tLo);
    split_f32<<<(F_ * F_ / 4) / 256, 256>>>(W, WHi, WLo);

    // 1) hidden = text @ W + b   (3-term fp16: hidden accurate to ~1e-6)
    gemm_mma<3, 0><<<dim3(F_ / 128, MTOT / 128, 1), 256, SMEM3>>>(
        tHi, tLo, WHi, WLo, F_, F_, F_, 0, 0,
        bias, nullptr, hHi, hLo);

    // 2) s, d per node
    sd_kernel<<<MTOT, 128>>>(hHi, hLo, a_src, a_dst, sv, dv);

    // 3) softmax probabilities -> fp16 hi
    prob_kernel<<<MTOT, 256>>>(adj, sv, dv, PHi);

    // 4) out = P @ hidden   (1-term fp16: Phi*Hhi)
    gemm_mma<1, 1><<<dim3(F_ / 128, N_ / 128, B_), 256, SMEM1>>>(
        PHi, nullptr, hHi, nullptr, N_, F_, N_, N_, N_,
        nullptr, out, nullptr, nullptr);
}

// round 7
// speedup vs baseline: 2.3692x; 1.2828x over previous
#include <cuda_runtime.h>
#include <cuda_fp16.h>
#include <cstdint>

#define B_    8
#define N_    2048
#define F_    512
#define MTOT  (B_ * N_)          // 16384
#define NEGV  (-10000.0f)
#define SLOPE 0.2f
#define FULLM 0xFFFFFFFFu

// ---------------- device scratch (sanctioned static-array path) -------------
__device__ __half g_tHi[(size_t)MTOT * F_];
__device__ __half g_WHi[(size_t)F_ * F_];
__device__ __half g_hHi[(size_t)MTOT * F_];   // hidden fp16, row-major
__device__ float g_ws[F_], g_wd[F_];          // W @ a_src, W @ a_dst
__device__ float g_sbdb[2];                   // b.a_src, b.a_dst
__device__ float g_sv[MTOT], g_dv[MTOT];
__device__ __half g_PHi[(size_t)MTOT * N_];

// ---------------- base-target PTX helpers ------------------------------------
__device__ __forceinline__ uint32_t smem_u32(const void* p) {
    uint32_t a;
    asm("{ .reg .u64 t; cvta.to.shared.u64 t, %1; cvt.u32.u64 %0, t; }"
        : "=r"(a) : "l"(p));
    return a;
}
__device__ __forceinline__ void cp16(uint32_t dst, const void* src) {
    asm volatile("cp.async.cg.shared.global [%0], [%1], 16;" :: "r"(dst), "l"(src));
}
#define CP_COMMIT() asm volatile("cp.async.commit_group;" ::: "memory")
#define CP_WAIT(n)  asm volatile("cp.async.wait_group %0;" :: "n"(n) : "memory")

#define LDSM4(r0, r1, r2, r3, addr) \
    asm volatile("ldmatrix.sync.aligned.m8n8.x4.shared.b16 {%0,%1,%2,%3}, [%4];" \
                 : "=r"(r0), "=r"(r1), "=r"(r2), "=r"(r3) : "r"(addr))
#define LDSM4T(r0, r1, r2, r3, addr) \
    asm volatile("ldmatrix.sync.aligned.m8n8.x4.trans.shared.b16 {%0,%1,%2,%3}, [%4];" \
                 : "=r"(r0), "=r"(r1), "=r"(r2), "=r"(r3) : "r"(addr))

#define MMA(d, a, b) \
    asm volatile("mma.sync.aligned.m16n8k16.row.col.f32.f16.f16.f32 " \
                 "{%0,%1,%2,%3}, {%4,%5,%6,%7}, {%8,%9}, {%0,%1,%2,%3};" \
                 : "+f"((d)[0]), "+f"((d)[1]), "+f"((d)[2]), "+f"((d)[3]) \
                 : "r"((a)[0]), "r"((a)[1]), "r"((a)[2]), "r"((a)[3]), \
                   "r"((b)[0]), "r"((b)[1]))

// ---------------- SMEM layout -------------------------------------------------
#define A_PITCH_B 80
#define B_PITCH_B 272
#define SZ_A (128 * A_PITCH_B)            // 10240
#define SZ_B (32 * B_PITCH_B)             // 8704
#define STAGES 3
#define BUF_STRIDE (SZ_A + SZ_B)          // 18944
#define SMEM_BYTES (STAGES * BUF_STRIDE)  // 56832

// ---------------- 1-term fp16 GEMM (mma.sync), CTA 128x128x32 ----------------
// C = Ahi * Bhi  (fp32 accumulate)
// MODE 0: hHi = fp16(C + bias)
// MODE 1: outF[row][512] = C  (fp32)
template<int MODE>
__global__ __launch_bounds__(256) void gemm_mma(
    const __half* __restrict__ Ahi, const __half* __restrict__ Bhi,
    int lda, int ldb, int K, int AZ, int BZ,
    const float* __restrict__ bias, float* __restrict__ outF,
    __half* __restrict__ hHi)
{
    extern __shared__ char sm[];
    const uint32_t smBase = smem_u32(sm);

    const int t = threadIdx.x;
    const int warp = t >> 5, lane = t & 31;
    const int wm = warp & 1, wn = warp >> 1;          // 2 x 4 warp grid

    const int nBase  = blockIdx.x * 128;
    const int aRow0  = blockIdx.y * 128 + blockIdx.z * AZ;
    const int bRow0  = blockIdx.z * BZ;

    float acc[4][4][4];
#pragma unroll
    for (int i = 0; i < 4; i++)
#pragma unroll
        for (int j = 0; j < 4; j++)
#pragma unroll
            for (int q = 0; q < 4; q++) acc[i][j][q] = 0.0f;

    // ---- per-thread load geometry ----
    const int rA = t >> 2, chA = t & 3;               // A rows rA, rA+64
    const int rB = t >> 4, chB = t & 15;              // B rows rB, rB+16
    const __half* pAh = Ahi + (size_t)(aRow0 + rA) * lda + chA * 8;
    const __half* pBh = Bhi + (size_t)(bRow0 + rB) * ldb + nBase + chB * 8;
    const uint32_t sA = smBase + rA * A_PITCH_B + chA * 16;
    const uint32_t sB = smBase + SZ_A + rB * B_PITCH_B + chB * 16;
    const size_t a64 = (size_t)64 * lda;
    const size_t b16 = (size_t)16 * ldb;

    auto load_tile = [&](int buf, int kt) {
        const size_t ka = (size_t)kt * 32;
        const size_t kb = (size_t)kt * 32 * ldb;
        const uint32_t ob = buf * BUF_STRIDE;
        cp16(sA + ob,                  pAh + ka);
        cp16(sA + ob + 64 * A_PITCH_B, pAh + ka + a64);
        cp16(sB + ob,                  pBh + kb);
        cp16(sB + ob + 16 * B_PITCH_B, pBh + kb + b16);
    };

    // per-lane ldmatrix address components
    const int aRowL  = lane & 15;
    const int aColB  = (lane >> 4) * 16;
    const int bRowL  = lane & 15;
    const int bColB  = (wn * 32 + (lane >> 4) * 8) * 2;

    const int ntiles = K / 32;
    load_tile(0, 0); CP_COMMIT();
    load_tile(1, 1); CP_COMMIT();

    int buf = 0;
    for (int kt = 0; kt < ntiles; kt++) {
        if (kt < ntiles - 1) { CP_WAIT(1); } else { CP_WAIT(0); }
        __syncthreads();

        if (kt + 2 < ntiles) {
            int nb = buf + 2; if (nb >= STAGES) nb -= STAGES;
            load_tile(nb, kt + 2);
            CP_COMMIT();
        }

        const uint32_t ob  = smBase + buf * BUF_STRIDE;
        const uint32_t obB = ob + SZ_A;

#pragma unroll
        for (int ks = 0; ks < 2; ks++) {
            uint32_t ahi[4][4];
#pragma unroll
            for (int mt = 0; mt < 4; mt++) {
                uint32_t ra = ob + (wm * 64 + mt * 16 + aRowL) * A_PITCH_B
                            + ks * 32 + aColB;
                LDSM4(ahi[mt][0], ahi[mt][1], ahi[mt][2], ahi[mt][3], ra);
            }
            uint32_t bhi[4][2];
#pragma unroll
            for (int bt = 0; bt < 2; bt++) {
                uint32_t rb = obB + (ks * 16 + bRowL) * B_PITCH_B + bColB + bt * 32;
                LDSM4T(bhi[bt*2][0], bhi[bt*2][1], bhi[bt*2+1][0], bhi[bt*2+1][1], rb);
            }
#pragma unroll
            for (int mt = 0; mt < 4; mt++)
#pragma unroll
                for (int nt = 0; nt < 4; nt++)
                    MMA(acc[mt][nt], ahi[mt], bhi[nt]);
        }
        buf++; if (buf >= STAGES) buf = 0;
    }

    // ---------------- epilogue ----------------
#pragma unroll
    for (int nt = 0; nt < 4; nt++) {
        int gCol = nBase + wn * 32 + nt * 8 + (lane & 3) * 2;
        float2 bv = make_float2(0.f, 0.f);
        if (MODE == 0) bv = *(const float2*)(bias + gCol);
#pragma unroll
        for (int mt = 0; mt < 4; mt++) {
            int gRow = aRow0 + wm * 64 + mt * 16 + (lane >> 2);
            if (MODE == 1) {
                *(float2*)(outF + (size_t)gRow * F_ + gCol) =
                    make_float2(acc[mt][nt][0], acc[mt][nt][1]);
                *(float2*)(outF + (size_t)(gRow + 8) * F_ + gCol) =
                    make_float2(acc[mt][nt][2], acc[mt][nt][3]);
            } else {
#pragma unroll
                for (int h = 0; h < 2; h++) {
                    __half2 vh;
                    vh.x = __float2half_rn(acc[mt][nt][h * 2]     + bv.x);
                    vh.y = __float2half_rn(acc[mt][nt][h * 2 + 1] + bv.y);
                    *(__half2*)(hHi + (size_t)(gRow + h * 8) * F_ + gCol) = vh;
                }
            }
        }
    }
}

// ---------------- prep: fp32 -> fp16 (hi only) --------------------------------
__global__ __launch_bounds__(256) void split_hi(const float* __restrict__ x,
                                                __half* __restrict__ hi) {
    size_t i = (size_t)blockIdx.x * 256 + threadIdx.x;   // one float4 each
    float4 v = ((const float4*)x)[i];
    __half2 a, b;
    a.x = __float2half_rn(v.x); a.y = __float2half_rn(v.y);
    b.x = __float2half_rn(v.z); b.y = __float2half_rn(v.w);
    __half2* ph = (__half2*)(hi + i * 4);
    ph[0] = a; ph[1] = b;
}

// ---------------- prep: ws = W @ a_src, wd = W @ a_dst (fp32) -----------------
// One warp per W row (fi); 4 warps per block.
__global__ __launch_bounds__(128) void prep_ws(
    const float* __restrict__ W, const float* __restrict__ a_src,
    const float* __restrict__ a_dst, float* __restrict__ ws, float* __restrict__ wd)
{
    int row = blockIdx.x * 4 + (threadIdx.x >> 5);
    int lane = threadIdx.x & 31;
    const float4* wr = (const float4*)(W + (size_t)row * F_);
    const float4* as = (const float4*)a_src;
    const float4* ad = (const float4*)a_dst;
    float s = 0.f, d = 0.f;
#pragma unroll
    for (int i = lane; i < F_ / 4; i += 32) {
        float4 w = wr[i], a = as[i], b = ad[i];
        s += w.x * a.x + w.y * a.y + w.z * a.z + w.w * a.w;
        d += w.x * b.x + w.y * b.y + w.z * b.z + w.w * b.w;
    }
#pragma unroll
    for (int o = 16; o; o >>= 1) {
        s += __shfl_xor_sync(FULLM, s, o);
        d += __shfl_xor_sync(FULLM, d, o);
    }
    if (lane == 0) { ws[row] = s; wd[row] = d; }
}

// ---------------- prep: sb = b.a_src, db = b.a_dst ----------------------------
__global__ __launch_bounds__(128) void prep_sb(
    const float* __restrict__ b, const float* __restrict__ a_src,
    const float* __restrict__ a_dst, float* __restrict__ sbdb)
{
    int t = threadIdx.x;
    const float4* bb = (const float4*)b;
    const float4* as = (const float4*)a_src;
    const float4* ad = (const float4*)a_dst;
    float4 v = bb[t], a = as[t], c = ad[t];
    float s = v.x * a.x + v.y * a.y + v.z * a.z + v.w * a.w;
    float d = v.x * c.x + v.y * c.y + v.z * c.z + v.w * c.w;
#pragma unroll
    for (int o = 16; o; o >>= 1) {
        s += __shfl_xor_sync(FULLM, s, o);
        d += __shfl_xor_sync(FULLM, d, o);
    }
    __shared__ float rs[4], rd[4];
    int lane = t & 31, wid = t >> 5;
    if (lane == 0) { rs[wid] = s; rd[wid] = d; }
    __syncthreads();
    if (t == 0) {
        sbdb[0] = rs[0] + rs[1] + rs[2] + rs[3];
        sbdb[1] = rd[0] + rd[1] + rd[2] + rd[3];
    }
}

// ---------------- s/d per node: fp32 GEMV over text ---------------------------
__global__ __launch_bounds__(128) void sd_gemv(
    const float* __restrict__ text, const float* __restrict__ ws,
    const float* __restrict__ wd, const float* __restrict__ sbdb,
    float* __restrict__ s, float* __restrict__ d)
{
    int row = blockIdx.x;
    int t = threadIdx.x;                         // one float4 per thread
    float4 x = ((const float4*)(text + (size_t)row * F_))[t];
    float4 a = ((const float4*)ws)[t];
    float4 c = ((const float4*)wd)[t];
    float ss = x.x * a.x + x.y * a.y + x.z * a.z + x.w * a.w;
    float dd = x.x * c.x + x.y * c.y + x.z * c.z + x.w * c.w;
#pragma unroll
    for (int o = 16; o; o >>= 1) {
        ss += __shfl_xor_sync(FULLM, ss, o);
        dd += __shfl_xor_sync(FULLM, dd, o);
    }
    __shared__ float rs[4], rd[4];
    int lane = t & 31, wid = t >> 5;
    if (lane == 0) { rs[wid] = ss; rd[wid] = dd; }
    __syncthreads();
    if (t == 0) {
        s[row] = rs[0] + rs[1] + rs[2] + rs[3] + sbdb[0];
        d[row] = rd[0] + rd[1] + rd[2] + rd[3] + sbdb[1];
    }
}

// ---------------- softmax probabilities -> fp16 (hi only) ---------------------
__global__ __launch_bounds__(256) void prob_kernel(
    const int* __restrict__ adj, const float* __restrict__ s,
    const float* __restrict__ dvec, __half* __restrict__ Phi)
{
    int row = blockIdx.x;
    int t = threadIdx.x;
    const int j0 = t * 8;
    const int4* arow = (const int4*)(adj + (size_t)row * N_ + j0);
    const float4* drow = (const float4*)(dvec + ((row >> 11) << 11) + j0);
    float si = s[row];

    int4 a0 = arow[0], a1 = arow[1];
    float4 d0 = drow[0], d1 = drow[1];
    int am[8] = {a0.x, a0.y, a0.z, a0.w, a1.x, a1.y, a1.z, a1.w};
    float dv[8] = {d0.x, d0.y, d0.z, d0.w, d1.x, d1.y, d1.z, d1.w};

    float sc[8];
#pragma unroll
    for (int q = 0; q < 8; q++) {
        float x = si + dv[q];
        x = (x >= 0.0f) ? x : SLOPE * x;
        sc[q] = am[q] ? NEGV : x;
    }

    __shared__ float redA[8], redB[8];
    int lane = t & 31, wid = t >> 5;
    float m = sc[0];
#pragma unroll
    for (int q = 1; q < 8; q++) m = fmaxf(m, sc[q]);
#pragma unroll
    for (int o = 16; o; o >>= 1) m = fmaxf(m, __shfl_xor_sync(FULLM, m, o));
    if (lane == 0) redA[wid] = m;
    __syncthreads();
    if (wid == 0) {
        float v = (lane < 8) ? redA[lane] : -3.4e38f;
#pragma unroll
        for (int o = 16; o; o >>= 1) v = fmaxf(v, __shfl_xor_sync(FULLM, v, o));
        if (lane == 0) redA[0] = v;
    }
    __syncthreads();
    m = redA[0];

    float l = 0.0f;
#pragma unroll
    for (int q = 0; q < 8; q++) { sc[q] = __expf(sc[q] - m); l += sc[q]; }
#pragma unroll
    for (int o = 16; o; o >>= 1) l += __shfl_xor_sync(FULLM, l, o);
    if (lane == 0) redB[wid] = l;
    __syncthreads();
    if (wid == 0) {
        float v = (lane < 8) ? redB[lane] : 0.0f;
#pragma unroll
        for (int o = 16; o; o >>= 1) v += __shfl_xor_sync(FULLM, v, o);
        if (lane == 0) redB[0] = v;
    }
    __syncthreads();
    float inv = 1.0f / redB[0];

    __half2 w[4];
#pragma unroll
    for (int q = 0; q < 4; q++) {
        w[q].x = __float2half_rn(sc[q * 2] * inv);
        w[q].y = __float2half_rn(sc[q * 2 + 1] * inv);
    }
    *(uint4*)(Phi + (size_t)row * N_ + j0) = *(uint4*)w;
}

// ---------------- launch -------------------------------------------------------
extern "C" void kernel_launch(void* const* d_in, const int* in_sizes, int n_in,
                              void* d_out, int out_size) {
    (void)in_sizes; (void)n_in; (void)out_size;
    const float* text  = (const float*)d_in[0];
    const int*   adj   = (const int*)d_in[1];
    const float* W     = (const float*)d_in[2];
    const float* bias  = (const float*)d_in[3];
    const float* a_src = (const float*)d_in[4];
    const float* a_dst = (const float*)d_in[5];
    float* out = (float*)d_out;

    __half *tHi, *WHi, *hHi, *PHi;
    float *ws, *wd, *sbdb, *sv, *dv;
    cudaGetSymbolAddress((void**)&tHi,  g_tHi);
    cudaGetSymbolAddress((void**)&WHi,  g_WHi);
    cudaGetSymbolAddress((void**)&hHi,  g_hHi);
    cudaGetSymbolAddress((void**)&ws,   g_ws);
    cudaGetSymbolAddress((void**)&wd,   g_wd);
    cudaGetSymbolAddress((void**)&sbdb, g_sbdb);
    cudaGetSymbolAddress((void**)&sv,   g_sv);
    cudaGetSymbolAddress((void**)&dv,   g_dv);
    cudaGetSymbolAddress((void**)&PHi,  g_PHi);

    static int smem_set = 0;
    if (!smem_set) {
        cudaFuncSetAttribute(gemm_mma<0>,
                             cudaFuncAttributeMaxDynamicSharedMemorySize, SMEM_BYTES);
        cudaFuncSetAttribute(gemm_mma<1>,
                             cudaFuncAttributeMaxDynamicSharedMemorySize, SMEM_BYTES);
        smem_set = 1;
    }

    // 0) preps: fp16 casts + score vectors (all independent)
    split_hi<<<(MTOT * F_ / 4) / 256, 256>>>(text, tHi);
    split_hi<<<(F_ * F_ / 4) / 256, 256>>>(W, WHi);
    prep_ws<<<F_ / 4, 128>>>(W, a_src, a_dst, ws, wd);
    prep_sb<<<1, 128>>>(bias, a_src, a_dst, sbdb);

    // 1) s, d per node — fp32 exact path, independent of hidden precision
    sd_gemv<<<MTOT, 128>>>(text, ws, wd, sbdb, sv, dv);

    // 2) softmax probabilities -> fp16
    prob_kernel<<<MTOT, 256>>>(adj, sv, dv, PHi);

    // 3) hidden = fp16(text @ W + b)   (1-term)
    gemm_mma<0><<<dim3(F_ / 128, MTOT / 128, 1), 256, SMEM_BYTES>>>(
        tHi, WHi, F_, F_, F_, 0, 0, bias, nullptr, hHi);

    // 4) out = P @ hidden   (1-term)
    gemm_mma<1><<<dim3(F_ / 128, N_ / 128, B_), 256, SMEM_BYTES>>>(
        PHi, hHi, N_, F_, N_, N_, N_, nullptr, out, nullptr);
}